// round 12
// baseline (speedup 1.0000x reference)
#include <cuda_runtime.h>
#include <cuda_bf16.h>
#include <math.h>
#include <stdint.h>

// ---------------------------------------------------------------------------
// ViT attention: TF32 mma.sync, pre-rounded tf32 operands, sigma-permuted
// contraction dims everywhere (all fragment loads vectorized: LDS.64/128),
// single-sync cp.async pipelines, flash-style attention.
// B=4, S=2048, E=768, H=12, D=64.
// d_out = attn_output [4,2048,768] ++ attn_weights [4,12,2048,2048].
//
// sigma (within each 8-group of a contraction/feature dim):
//   logical n -> position ((n&3)<<1)|((n>>2)&1)   (t <-> 2t, 4+t <-> 2t+1)
// so an mma fragment k-pair (t, 4+t) is CONTIGUOUS in memory.
// ---------------------------------------------------------------------------

#define BATCH     4
#define SEQ       2048
#define EMB       768
#define HEADS     12
#define HDIM      64
#define MTOK      (BATCH * SEQ)
#define BH        (BATCH * HEADS)
#define SCALE_F   0.125f

#define PAD       36      // projection smem stride
#define KSTR      72      // K/V tile stride
#define VSTR      72
#define PSBLK     132     // Ps words per (mt,chunk) block

// Scratch (device globals). All tf32-rounded.
// g_q/g_k: sigma-permuted along d (head dim). g_v plain.
// g_hsr/g_wq/g_wk/g_wv/g_wo: sigma-permuted along k (EMB contraction).
// g_att: sigma-permuted along d (EMB feature dim, per 8-group).
__device__ float g_q[MTOK * EMB];
__device__ float g_k[MTOK * EMB];
__device__ float g_v[MTOK * EMB];
__device__ float g_att[MTOK * EMB];
__device__ float g_inv[BH * SEQ];
__device__ float g_hsr[MTOK * EMB];
__device__ float g_wq[EMB * EMB];
__device__ float g_wk[EMB * EMB];
__device__ float g_wv[EMB * EMB];
__device__ float g_wo[EMB * EMB];

// ---------------------------------------------------------------------------
__device__ __forceinline__ void cp16(void* s, const void* g) {
    uint32_t sa = (uint32_t)__cvta_generic_to_shared(s);
    asm volatile("cp.async.cg.shared.global [%0], [%1], 16;\n" :: "r"(sa), "l"(g));
}
__device__ __forceinline__ void cp_commit() {
    asm volatile("cp.async.commit_group;\n" ::: "memory");
}
__device__ __forceinline__ void cp_wait1() {
    asm volatile("cp.async.wait_group 1;\n" ::: "memory");
}
__device__ __forceinline__ void cp_wait0() {
    asm volatile("cp.async.wait_group 0;\n" ::: "memory");
}

__device__ __forceinline__ float rnd(float x) {
    float r;
    asm("cvt.rna.tf32.f32 %0, %1;" : "=f"(r) : "f"(x));
    return r;
}
__device__ __forceinline__ uint32_t raw(float x) { return __float_as_uint(x); }

__device__ __forceinline__ void mma_tf32(float c[4],
                                         uint32_t a0, uint32_t a1, uint32_t a2, uint32_t a3,
                                         uint32_t b0, uint32_t b1) {
    asm volatile(
        "mma.sync.aligned.m16n8k8.row.col.f32.tf32.tf32.f32 "
        "{%0,%1,%2,%3}, {%4,%5,%6,%7}, {%8,%9}, {%0,%1,%2,%3};\n"
        : "+f"(c[0]), "+f"(c[1]), "+f"(c[2]), "+f"(c[3])
        : "r"(a0), "r"(a1), "r"(a2), "r"(a3), "r"(b0), "r"(b1));
}

// ---------------------------------------------------------------------------
// Pre-round + sigma-permute along the row (last, contiguous) dim.
// Each thread handles one 8-group (32B in, 32B out, fully coalesced).
// out[sigma(n)] = rnd(in[n]):
//   out = {in0, in4, in1, in5, in2, in6, in3, in7}
// ---------------------------------------------------------------------------
__global__ void round_perm_kernel(const float4* __restrict__ in,
                                  float4* __restrict__ out, int n8) {
    int i = blockIdx.x * blockDim.x + threadIdx.x;
    if (i < n8) {
        float4 lo = in[2 * i], hi = in[2 * i + 1];
        float4 olo, ohi;
        olo.x = rnd(lo.x); olo.y = rnd(hi.x); olo.z = rnd(lo.y); olo.w = rnd(hi.y);
        ohi.x = rnd(lo.z); ohi.y = rnd(hi.z); ohi.z = rnd(lo.w); ohi.w = rnd(hi.w);
        out[2 * i]     = olo;
        out[2 * i + 1] = ohi;
    }
}

// ---------------------------------------------------------------------------
// Projection GEMM: C = A @ W^T + bias.  A and W sigma-permuted along k =>
// all fragment loads are LDS.64. 128x128 tile, 8 warps, 3-stage cp.async,
// single sync per iteration.
// MODE 0: plain fp32 store. MODE 1: tf32-rounded + sigma on n (g_q/g_k).
// MODE 2: tf32-rounded plain (g_v).
// ---------------------------------------------------------------------------
template <int MODE>
__global__ __launch_bounds__(256, 2)
void gemm_xwT_tc(const float* __restrict__ A,
                 const float* __restrict__ W,
                 const float* __restrict__ bias,
                 float* __restrict__ C,
                 int M, int N, int K) {
    extern __shared__ __align__(16) float sm[];
    float (*As)[128][PAD] = (float (*)[128][PAD])sm;
    float (*Ws)[128][PAD] = (float (*)[128][PAD])(sm + 3 * 128 * PAD);

    const int m0 = blockIdx.y * 128;
    const int n0 = blockIdx.x * 128;
    const int tid = threadIdx.x;
    const int wid = tid >> 5;
    const int lane = tid & 31;
    const int wm = (wid >> 1) * 32;
    const int wn = (wid & 1) * 64;
    const int g = lane >> 2;
    const int t = lane & 3;
    const int nk = K >> 5;

    float acc[2][8][4] = {};

    #pragma unroll
    for (int s = 0; s < 2; s++) {
        const int k0 = s * 32;
        #pragma unroll
        for (int i = 0; i < 4; i++) {
            int idx = tid + i * 256, r = idx >> 3, c4 = idx & 7;
            cp16(&As[s][r][c4 * 4], A + (size_t)(m0 + r) * K + k0 + c4 * 4);
        }
        #pragma unroll
        for (int i = 0; i < 4; i++) {
            int idx = tid + i * 256, r = idx >> 3, c4 = idx & 7;
            cp16(&Ws[s][r][c4 * 4], W + (size_t)(n0 + r) * K + k0 + c4 * 4);
        }
        cp_commit();
    }

    for (int kt = 0; kt < nk; kt++) {
        cp_wait1();
        __syncthreads();

        if (kt + 2 < nk) {
            const int sb = (kt + 2) % 3;
            const int k0 = (kt + 2) * 32;
            #pragma unroll
            for (int i = 0; i < 4; i++) {
                int idx = tid + i * 256, r = idx >> 3, c4 = idx & 7;
                cp16(&As[sb][r][c4 * 4], A + (size_t)(m0 + r) * K + k0 + c4 * 4);
            }
            #pragma unroll
            for (int i = 0; i < 4; i++) {
                int idx = tid + i * 256, r = idx >> 3, c4 = idx & 7;
                cp16(&Ws[sb][r][c4 * 4], W + (size_t)(n0 + r) * K + k0 + c4 * 4);
            }
        }
        cp_commit();

        const int buf = kt % 3;
        #pragma unroll
        for (int kk = 0; kk < 4; kk++) {
            const int kb = kk * 8;
            uint32_t a[2][4], b[8][2];
            #pragma unroll
            for (int mi = 0; mi < 2; mi++) {
                int row = wm + mi * 16;
                float2 lo = *(const float2*)&As[buf][row + g][kb + 2 * t];
                float2 hi = *(const float2*)&As[buf][row + 8 + g][kb + 2 * t];
                a[mi][0] = raw(lo.x);   // logical k = t
                a[mi][1] = raw(hi.x);
                a[mi][2] = raw(lo.y);   // logical k = 4+t
                a[mi][3] = raw(hi.y);
            }
            #pragma unroll
            for (int ni = 0; ni < 8; ni++) {
                int col = wn + ni * 8;
                float2 bv = *(const float2*)&Ws[buf][col + g][kb + 2 * t];
                b[ni][0] = raw(bv.x);
                b[ni][1] = raw(bv.y);
            }
            #pragma unroll
            for (int mi = 0; mi < 2; mi++)
                #pragma unroll
                for (int ni = 0; ni < 8; ni++)
                    mma_tf32(acc[mi][ni], a[mi][0], a[mi][1], a[mi][2], a[mi][3],
                             b[ni][0], b[ni][1]);
        }
    }

    #pragma unroll
    for (int mi = 0; mi < 2; mi++) {
        #pragma unroll
        for (int ni = 0; ni < 8; ni++) {
            int m = m0 + wm + mi * 16 + g;
            int n = n0 + wn + ni * 8 + t * 2;
            float b0 = __ldg(&bias[n]), b1 = __ldg(&bias[n + 1]);
            float v0 = acc[mi][ni][0] + b0;
            float v1 = acc[mi][ni][1] + b1;
            float v2 = acc[mi][ni][2] + b0;
            float v3 = acc[mi][ni][3] + b1;
            if (MODE == 0) {
                C[(size_t)m * N + n]           = v0;
                C[(size_t)m * N + n + 1]       = v1;
                C[(size_t)(m + 8) * N + n]     = v2;
                C[(size_t)(m + 8) * N + n + 1] = v3;
            } else if (MODE == 2) {
                C[(size_t)m * N + n]           = rnd(v0);
                C[(size_t)m * N + n + 1]       = rnd(v1);
                C[(size_t)(m + 8) * N + n]     = rnd(v2);
                C[(size_t)(m + 8) * N + n + 1] = rnd(v3);
            } else {
                // sigma on n within 8-group
                int nb = n & ~7;
                int p0 = nb + (((n & 3) << 1) | ((n >> 2) & 1));
                int p1 = p0 + 2;
                C[(size_t)m * N + p0]       = rnd(v0);
                C[(size_t)m * N + p1]       = rnd(v1);
                C[(size_t)(m + 8) * N + p0] = rnd(v2);
                C[(size_t)(m + 8) * N + p1] = rnd(v3);
            }
        }
    }
}

// ---------------------------------------------------------------------------
// Q a-fragments (sigma-permuted g_q): LDG.64 pairs.
// ---------------------------------------------------------------------------
__device__ __forceinline__ void load_q_frags(uint32_t qa[2][8][4],
                                             int b, int h, int qbase,
                                             int g, int t) {
    #pragma unroll
    for (int mi = 0; mi < 2; mi++) {
        const float* qp = g_q + (size_t)(b * SEQ + qbase + mi * 16) * EMB + h * HDIM;
        #pragma unroll
        for (int d8 = 0; d8 < 8; d8++) {
            int c = d8 * 8 + 2 * t;
            float2 lo = *(const float2*)&qp[(size_t)g * EMB + c];
            float2 hi = *(const float2*)&qp[(size_t)(8 + g) * EMB + c];
            qa[mi][d8][0] = raw(lo.x);
            qa[mi][d8][1] = raw(hi.x);
            qa[mi][d8][2] = raw(lo.y);
            qa[mi][d8][3] = raw(hi.y);
        }
    }
}

// ---------------------------------------------------------------------------
// rowsum: g_inv = 1/rowsum(exp(QK^T*scale)). Q in regs; K smem LDS.64.
// grid (SEQ/128, BH), 8 warps 4m x 2n.
// ---------------------------------------------------------------------------
__global__ __launch_bounds__(256, 2)
void rowsum_tc() {
    extern __shared__ __align__(16) float sm[];
    float* Ks = sm;                       // [2][64][KSTR]
    __shared__ float s_red[128];

    const int bh = blockIdx.y;
    const int b  = bh / HEADS;
    const int h  = bh % HEADS;
    const int q0 = blockIdx.x * 128;
    const int tid = threadIdx.x;
    const int wid = tid >> 5;
    const int lane = tid & 31;
    const int wm = (wid >> 1) * 32;
    const int wn = (wid & 1) * 32;
    const int g = lane >> 2;
    const int t = lane & 3;

    if (tid < 128) s_red[tid] = 0.f;

    #pragma unroll
    for (int i = 0; i < 4; i++) {
        int idx = tid + i * 256, r = idx >> 4, c4 = idx & 15;
        cp16(&Ks[r * KSTR + c4 * 4],
             g_k + (size_t)(b * SEQ + r) * EMB + h * HDIM + c4 * 4);
    }
    cp_commit();

    uint32_t qa[2][8][4];
    load_q_frags(qa, b, h, q0 + wm, g, t);

    float rsum[2][2] = {};

    for (int kt = 0; kt < SEQ / 64; kt++) {
        cp_wait0();
        __syncthreads();

        if (kt + 1 < SEQ / 64) {
            float* Kn = Ks + ((kt + 1) & 1) * 64 * KSTR;
            const int r0 = (kt + 1) * 64;
            #pragma unroll
            for (int i = 0; i < 4; i++) {
                int idx = tid + i * 256, r = idx >> 4, c4 = idx & 15;
                cp16(&Kn[r * KSTR + c4 * 4],
                     g_k + (size_t)(b * SEQ + r0 + r) * EMB + h * HDIM + c4 * 4);
            }
            cp_commit();
        }

        const float* Kb = Ks + (kt & 1) * 64 * KSTR;
        float acc[2][4][4] = {};

        #pragma unroll
        for (int d8 = 0; d8 < 8; d8++) {
            const int kb = d8 * 8;
            uint32_t bb[4][2];
            #pragma unroll
            for (int ni = 0; ni < 4; ni++) {
                int col = wn + ni * 8;
                float2 kv = *(const float2*)&Kb[(col + g) * KSTR + kb + 2 * t];
                bb[ni][0] = raw(kv.x);
                bb[ni][1] = raw(kv.y);
            }
            #pragma unroll
            for (int mi = 0; mi < 2; mi++)
                #pragma unroll
                for (int ni = 0; ni < 4; ni++)
                    mma_tf32(acc[mi][ni],
                             qa[mi][d8][0], qa[mi][d8][1], qa[mi][d8][2], qa[mi][d8][3],
                             bb[ni][0], bb[ni][1]);
        }

        #pragma unroll
        for (int mi = 0; mi < 2; mi++)
            #pragma unroll
            for (int ni = 0; ni < 4; ni++) {
                rsum[mi][0] += __expf(acc[mi][ni][0] * SCALE_F)
                             + __expf(acc[mi][ni][1] * SCALE_F);
                rsum[mi][1] += __expf(acc[mi][ni][2] * SCALE_F)
                             + __expf(acc[mi][ni][3] * SCALE_F);
            }
    }

    #pragma unroll
    for (int mi = 0; mi < 2; mi++)
        #pragma unroll
        for (int j = 0; j < 2; j++) {
            rsum[mi][j] += __shfl_xor_sync(0xffffffffu, rsum[mi][j], 1);
            rsum[mi][j] += __shfl_xor_sync(0xffffffffu, rsum[mi][j], 2);
        }

    if (t == 0) {
        #pragma unroll
        for (int mi = 0; mi < 2; mi++) {
            atomicAdd(&s_red[wm + mi * 16 + g],     rsum[mi][0]);
            atomicAdd(&s_red[wm + mi * 16 + 8 + g], rsum[mi][1]);
        }
    }
    __syncthreads();
    if (tid < 128)
        g_inv[(size_t)bh * SEQ + q0 + tid] = 1.0f / s_red[tid];
}

// ---------------------------------------------------------------------------
// flash: scores (Q regs, K LDS.64), p written to gmem from c-frags + Ps
// frag-major; PV a-frags LDS.128. g_att written sigma-permuted along d.
// grid (SEQ/64, BH), 8 warps: wm=(wid>>2)*32, wn=(wid&3)*16.
// ---------------------------------------------------------------------------
__global__ __launch_bounds__(256, 2)
void flash_pv_tc(float* __restrict__ wbuf) {
    extern __shared__ __align__(16) float sm[];
    float* Ks = sm;                               // [2][64][KSTR]
    float* Vs = Ks + 2 * 64 * KSTR;               // [2][64][VSTR]
    float* Ps = Vs + 2 * 64 * VSTR;               // [32][PSBLK]

    const int bh = blockIdx.y;
    const int b  = bh / HEADS;
    const int h  = bh % HEADS;
    const int q0 = blockIdx.x * 64;
    const int tid = threadIdx.x;
    const int wid = tid >> 5;
    const int lane = tid & 31;
    const int wm = (wid >> 2) * 32;
    const int wn = (wid & 3) * 16;
    const int g = lane >> 2;
    const int t = lane & 3;

    #pragma unroll
    for (int i = 0; i < 4; i++) {
        int idx = tid + i * 256, r = idx >> 4, c4 = idx & 15;
        cp16(&Ks[r * KSTR + c4 * 4],
             g_k + (size_t)(b * SEQ + r) * EMB + h * HDIM + c4 * 4);
        cp16(&Vs[r * VSTR + c4 * 4],
             g_v + (size_t)(b * SEQ + r) * EMB + h * HDIM + c4 * 4);
    }
    cp_commit();

    uint32_t qa[2][8][4];
    load_q_frags(qa, b, h, q0 + wm, g, t);

    float iv[2][2];
    #pragma unroll
    for (int mi = 0; mi < 2; mi++) {
        iv[mi][0] = g_inv[(size_t)bh * SEQ + q0 + wm + mi * 16 + g];
        iv[mi][1] = g_inv[(size_t)bh * SEQ + q0 + wm + mi * 16 + 8 + g];
    }

    float* prow = wbuf + (size_t)bh * SEQ * SEQ;
    float acc_o[2][2][4] = {};

    const int tp0 = (2 * t) & 3;
    const int tp1 = (2 * t + 1) & 3;
    const int j0  = 2 * (t >> 1);

    for (int kt = 0; kt < SEQ / 64; kt++) {
        cp_wait0();
        __syncthreads();

        if (kt + 1 < SEQ / 64) {
            const int nb = (kt + 1) & 1;
            const int r0 = (kt + 1) * 64;
            float* Kn = Ks + nb * 64 * KSTR;
            float* Vn = Vs + nb * 64 * VSTR;
            #pragma unroll
            for (int i = 0; i < 4; i++) {
                int idx = tid + i * 256, r = idx >> 4, c4 = idx & 15;
                cp16(&Kn[r * KSTR + c4 * 4],
                     g_k + (size_t)(b * SEQ + r0 + r) * EMB + h * HDIM + c4 * 4);
                cp16(&Vn[r * VSTR + c4 * 4],
                     g_v + (size_t)(b * SEQ + r0 + r) * EMB + h * HDIM + c4 * 4);
            }
            cp_commit();
        }

        const float* Kb = Ks + (kt & 1) * 64 * KSTR;
        const float* Vb = Vs + (kt & 1) * 64 * VSTR;

        float acc_s[2][2][4] = {};
        #pragma unroll
        for (int d8 = 0; d8 < 8; d8++) {
            const int kb = d8 * 8;
            uint32_t bb[2][2];
            #pragma unroll
            for (int ni = 0; ni < 2; ni++) {
                int col = wn + ni * 8;
                float2 kv = *(const float2*)&Kb[(col + g) * KSTR + kb + 2 * t];
                bb[ni][0] = raw(kv.x);
                bb[ni][1] = raw(kv.y);
            }
            #pragma unroll
            for (int mi = 0; mi < 2; mi++)
                #pragma unroll
                for (int ni = 0; ni < 2; ni++)
                    mma_tf32(acc_s[mi][ni],
                             qa[mi][d8][0], qa[mi][d8][1], qa[mi][d8][2], qa[mi][d8][3],
                             bb[ni][0], bb[ni][1]);
        }

        #pragma unroll
        for (int mi = 0; mi < 2; mi++) {
            const int mt = (wm >> 4) + mi;
            const int r0g = q0 + wm + mi * 16 + g;
            #pragma unroll
            for (int ni = 0; ni < 2; ni++) {
                const int c0 = wn + ni * 8 + 2 * t;
                const int chunk = (wn >> 3) + ni;
                float p00 = rnd(__expf(acc_s[mi][ni][0] * SCALE_F) * iv[mi][0]);
                float p01 = rnd(__expf(acc_s[mi][ni][1] * SCALE_F) * iv[mi][0]);
                float p10 = rnd(__expf(acc_s[mi][ni][2] * SCALE_F) * iv[mi][1]);
                float p11 = rnd(__expf(acc_s[mi][ni][3] * SCALE_F) * iv[mi][1]);
                *(float2*)&prow[(size_t)r0g * SEQ + kt * 64 + c0]       = make_float2(p00, p01);
                *(float2*)&prow[(size_t)(r0g + 8) * SEQ + kt * 64 + c0] = make_float2(p10, p11);
                float* pb = &Ps[(mt * 8 + chunk) * PSBLK];
                *(float2*)&pb[(g * 4 + tp0) * 4 + j0] = make_float2(p00, p10);
                *(float2*)&pb[(g * 4 + tp1) * 4 + j0] = make_float2(p01, p11);
            }
        }
        __syncthreads();

        #pragma unroll
        for (int d8 = 0; d8 < 8; d8++) {
            const int kb = d8 * 8;
            uint32_t a[2][4];
            #pragma unroll
            for (int mi = 0; mi < 2; mi++) {
                const int mt = (wm >> 4) + mi;
                float4 av = *(const float4*)&Ps[(mt * 8 + d8) * PSBLK + lane * 4];
                a[mi][0] = raw(av.x);
                a[mi][1] = raw(av.y);
                a[mi][2] = raw(av.z);
                a[mi][3] = raw(av.w);
            }
            uint32_t bb[2][2];
            #pragma unroll
            for (int ni = 0; ni < 2; ni++) {
                int col = wn + ni * 8;
                bb[ni][0] = raw(Vb[(kb + t) * VSTR + col + g]);
                bb[ni][1] = raw(Vb[(kb + 4 + t) * VSTR + col + g]);
            }
            #pragma unroll
            for (int mi = 0; mi < 2; mi++)
                #pragma unroll
                for (int ni = 0; ni < 2; ni++)
                    mma_tf32(acc_o[mi][ni], a[mi][0], a[mi][1], a[mi][2], a[mi][3],
                             bb[ni][0], bb[ni][1]);
        }
    }

    // epilogue: g_att sigma-permuted along d (within 8-groups)
    // logical cols: 2t (acc[0]/acc[2]), 2t+1 (acc[1]/acc[3]);
    // sigma(2t) = ((2t&3)<<1)|((2t>>2)&1), sigma(2t+1) = sigma(2t)+2.
    const int sp0 = (((2 * t) & 3) << 1) | (((2 * t) >> 2) & 1);
    #pragma unroll
    for (int mi = 0; mi < 2; mi++) {
        #pragma unroll
        for (int ni = 0; ni < 2; ni++) {
            int m = q0 + wm + mi * 16 + g;
            int dbase = wn + ni * 8;
            float* o0 = g_att + (size_t)(b * SEQ + m) * EMB + h * HDIM + dbase;
            float* o1 = g_att + (size_t)(b * SEQ + m + 8) * EMB + h * HDIM + dbase;
            o0[sp0]     = rnd(acc_o[mi][ni][0]);
            o0[sp0 + 2] = rnd(acc_o[mi][ni][1]);
            o1[sp0]     = rnd(acc_o[mi][ni][2]);
            o1[sp0 + 2] = rnd(acc_o[mi][ni][3]);
        }
    }
}

// ---------------------------------------------------------------------------
// launch
// ---------------------------------------------------------------------------
extern "C" void kernel_launch(void* const* d_in, const int* in_sizes, int n_in,
                              void* d_out, int out_size) {
    (void)in_sizes; (void)n_in; (void)out_size;

    const float* hs = (const float*)d_in[0];
    const float* Wq = (const float*)d_in[1];
    const float* bq = (const float*)d_in[2];
    const float* Wk = (const float*)d_in[3];
    const float* bk = (const float*)d_in[4];
    const float* Wv = (const float*)d_in[5];
    const float* bv = (const float*)d_in[6];
    const float* Wo = (const float*)d_in[7];
    const float* bo = (const float*)d_in[8];

    float* out      = (float*)d_out;
    float* attn_out = out;
    float* wbuf     = out + (size_t)MTOK * EMB;

    float* dq, * dk, * dv, * datt, * dhsr, * dwq, * dwk, * dwv, * dwo;
    cudaGetSymbolAddress((void**)&dq,   g_q);
    cudaGetSymbolAddress((void**)&dk,   g_k);
    cudaGetSymbolAddress((void**)&dv,   g_v);
    cudaGetSymbolAddress((void**)&datt, g_att);
    cudaGetSymbolAddress((void**)&dhsr, g_hsr);
    cudaGetSymbolAddress((void**)&dwq,  g_wq);
    cudaGetSymbolAddress((void**)&dwk,  g_wk);
    cudaGetSymbolAddress((void**)&dwv,  g_wv);
    cudaGetSymbolAddress((void**)&dwo,  g_wo);

    const int smem_gemm  = (3 * 128 * PAD + 3 * 128 * PAD) * 4;                 // 110592
    const int smem_rsum  = (2 * 64 * KSTR) * 4;                                 // 36864
    const int smem_flash = (2 * 64 * KSTR + 2 * 64 * VSTR + 32 * PSBLK) * 4;    // 90624

    cudaFuncSetAttribute(gemm_xwT_tc<0>, cudaFuncAttributeMaxDynamicSharedMemorySize, smem_gemm);
    cudaFuncSetAttribute(gemm_xwT_tc<1>, cudaFuncAttributeMaxDynamicSharedMemorySize, smem_gemm);
    cudaFuncSetAttribute(gemm_xwT_tc<2>, cudaFuncAttributeMaxDynamicSharedMemorySize, smem_gemm);
    cudaFuncSetAttribute(rowsum_tc,   cudaFuncAttributeMaxDynamicSharedMemorySize, smem_rsum);
    cudaFuncSetAttribute(flash_pv_tc, cudaFuncAttributeMaxDynamicSharedMemorySize, smem_flash);

    // pre-round + sigma-permute along k (contiguous dim) for all GEMM inputs
    const int n8_hs = MTOK * EMB / 8;
    const int n8_w  = EMB * EMB / 8;
    round_perm_kernel<<<(n8_hs + 255) / 256, 256>>>((const float4*)hs, (float4*)dhsr, n8_hs);
    round_perm_kernel<<<(n8_w + 255) / 256, 256>>>((const float4*)Wq, (float4*)dwq, n8_w);
    round_perm_kernel<<<(n8_w + 255) / 256, 256>>>((const float4*)Wk, (float4*)dwk, n8_w);
    round_perm_kernel<<<(n8_w + 255) / 256, 256>>>((const float4*)Wv, (float4*)dwv, n8_w);
    round_perm_kernel<<<(n8_w + 255) / 256, 256>>>((const float4*)Wo, (float4*)dwo, n8_w);

    dim3 gproj(EMB / 128, MTOK / 128);      // (6, 64)

    gemm_xwT_tc<1><<<gproj, 256, smem_gemm>>>(dhsr, dwq, bq, dq, MTOK, EMB, EMB);
    gemm_xwT_tc<1><<<gproj, 256, smem_gemm>>>(dhsr, dwk, bk, dk, MTOK, EMB, EMB);
    gemm_xwT_tc<2><<<gproj, 256, smem_gemm>>>(dhsr, dwv, bv, dv, MTOK, EMB, EMB);

    rowsum_tc<<<dim3(SEQ / 128, BH), 256, smem_rsum>>>();

    flash_pv_tc<<<dim3(SEQ / 64, BH), 256, smem_flash>>>(wbuf);

    gemm_xwT_tc<0><<<gproj, 256, smem_gemm>>>(datt, dwo, bo, attn_out, MTOK, EMB, EMB);
}

// round 13
// speedup vs baseline: 1.1172x; 1.1172x over previous
#include <cuda_runtime.h>
#include <cuda_bf16.h>
#include <math.h>
#include <stdint.h>

// ---------------------------------------------------------------------------
// ViT attention: TF32 mma.sync, pre-rounded tf32 operands, sigma-permuted
// Q/K head-dim layouts (vector fragment loads in attention), fragment-major
// P staging, single-sync cp.async pipelines. QKV projections fused into one
// launch; all pre-rounding fused into one launch.
// B=4, S=2048, E=768, H=12, D=64.
// d_out = attn_output [4,2048,768] ++ attn_weights [4,12,2048,2048].
// ---------------------------------------------------------------------------

#define BATCH     4
#define SEQ       2048
#define EMB       768
#define HEADS     12
#define HDIM      64
#define MTOK      (BATCH * SEQ)
#define BH        (BATCH * HEADS)
#define SCALE_F   0.125f

#define PAD       36      // projection smem stride (LDS.32 conflict-free)
#define KSTR      72      // K/V tile stride (conflict-free LDS.64)
#define VSTR      72
#define PSBLK     132     // Ps words per (mt,chunk) block

// Scratch (device globals). All tf32-rounded.
// g_q/g_k sigma-permuted along d; g_v/g_att plain.
__device__ float g_q[MTOK * EMB];
__device__ float g_k[MTOK * EMB];
__device__ float g_v[MTOK * EMB];
__device__ float g_att[MTOK * EMB];
__device__ float g_inv[BH * SEQ];
__device__ float g_hsr[MTOK * EMB];
__device__ float g_wq[EMB * EMB];
__device__ float g_wk[EMB * EMB];
__device__ float g_wv[EMB * EMB];
__device__ float g_wo[EMB * EMB];

// ---------------------------------------------------------------------------
__device__ __forceinline__ void cp16(void* s, const void* g) {
    uint32_t sa = (uint32_t)__cvta_generic_to_shared(s);
    asm volatile("cp.async.cg.shared.global [%0], [%1], 16;\n" :: "r"(sa), "l"(g));
}
__device__ __forceinline__ void cp_commit() {
    asm volatile("cp.async.commit_group;\n" ::: "memory");
}
__device__ __forceinline__ void cp_wait1() {
    asm volatile("cp.async.wait_group 1;\n" ::: "memory");
}
__device__ __forceinline__ void cp_wait0() {
    asm volatile("cp.async.wait_group 0;\n" ::: "memory");
}

__device__ __forceinline__ float rnd(float x) {
    float r;
    asm("cvt.rna.tf32.f32 %0, %1;" : "=f"(r) : "f"(x));
    return r;
}
__device__ __forceinline__ uint32_t raw(float x) { return __float_as_uint(x); }

__device__ __forceinline__ void mma_tf32(float c[4],
                                         uint32_t a0, uint32_t a1, uint32_t a2, uint32_t a3,
                                         uint32_t b0, uint32_t b1) {
    asm volatile(
        "mma.sync.aligned.m16n8k8.row.col.f32.tf32.tf32.f32 "
        "{%0,%1,%2,%3}, {%4,%5,%6,%7}, {%8,%9}, {%0,%1,%2,%3};\n"
        : "+f"(c[0]), "+f"(c[1]), "+f"(c[2]), "+f"(c[3])
        : "r"(a0), "r"(a1), "r"(a2), "r"(a3), "r"(b0), "r"(b1));
}

// ---------------------------------------------------------------------------
// Fused pre-round: hs + 4 weight matrices in one launch. Region dispatch by
// flat float4 index.
// ---------------------------------------------------------------------------
__global__ void round_all_kernel(const float4* __restrict__ hs,
                                 const float4* __restrict__ wq,
                                 const float4* __restrict__ wk,
                                 const float4* __restrict__ wv,
                                 const float4* __restrict__ wo,
                                 float4* __restrict__ dhsr,
                                 float4* __restrict__ dwq,
                                 float4* __restrict__ dwk,
                                 float4* __restrict__ dwv,
                                 float4* __restrict__ dwo,
                                 int n4_hs, int n4_w) {
    int i = blockIdx.x * blockDim.x + threadIdx.x;
    const float4* in;
    float4* out;
    int j = i;
    if (j < n4_hs)            { in = hs; out = dhsr; }
    else if ((j -= n4_hs) < n4_w)  { in = wq; out = dwq; }
    else if ((j -= n4_w) < n4_w)   { in = wk; out = dwk; }
    else if ((j -= n4_w) < n4_w)   { in = wv; out = dwv; }
    else if ((j -= n4_w) < n4_w)   { in = wo; out = dwo; }
    else return;
    float4 v = in[j];
    v.x = rnd(v.x); v.y = rnd(v.y); v.z = rnd(v.z); v.w = rnd(v.w);
    out[j] = v;
}

// ---------------------------------------------------------------------------
// Shared GEMM mainloop body (A,W pre-rounded; LDS.32 conflict-free frags).
// Epilogue mode: 0 plain fp32, 1 rounded+sigma(n), 2 rounded plain.
// ---------------------------------------------------------------------------
__device__ __forceinline__ void gemm_body(const float* __restrict__ A,
                                          const float* __restrict__ W,
                                          const float* __restrict__ bias,
                                          float* __restrict__ C,
                                          int M, int N, int K,
                                          int m0, int n0, int mode,
                                          float* sm) {
    float (*As)[128][PAD] = (float (*)[128][PAD])sm;
    float (*Ws)[128][PAD] = (float (*)[128][PAD])(sm + 3 * 128 * PAD);

    const int tid = threadIdx.x;
    const int wid = tid >> 5;
    const int lane = tid & 31;
    const int wm = (wid >> 1) * 32;
    const int wn = (wid & 1) * 64;
    const int g = lane >> 2;
    const int t = lane & 3;
    const int nk = K >> 5;

    float acc[2][8][4] = {};

    #pragma unroll
    for (int s = 0; s < 2; s++) {
        const int k0 = s * 32;
        #pragma unroll
        for (int i = 0; i < 4; i++) {
            int idx = tid + i * 256, r = idx >> 3, c4 = idx & 7;
            cp16(&As[s][r][c4 * 4], A + (size_t)(m0 + r) * K + k0 + c4 * 4);
        }
        #pragma unroll
        for (int i = 0; i < 4; i++) {
            int idx = tid + i * 256, r = idx >> 3, c4 = idx & 7;
            cp16(&Ws[s][r][c4 * 4], W + (size_t)(n0 + r) * K + k0 + c4 * 4);
        }
        cp_commit();
    }

    for (int kt = 0; kt < nk; kt++) {
        cp_wait1();
        __syncthreads();

        if (kt + 2 < nk) {
            const int sb = (kt + 2) % 3;
            const int k0 = (kt + 2) * 32;
            #pragma unroll
            for (int i = 0; i < 4; i++) {
                int idx = tid + i * 256, r = idx >> 3, c4 = idx & 7;
                cp16(&As[sb][r][c4 * 4], A + (size_t)(m0 + r) * K + k0 + c4 * 4);
            }
            #pragma unroll
            for (int i = 0; i < 4; i++) {
                int idx = tid + i * 256, r = idx >> 3, c4 = idx & 7;
                cp16(&Ws[sb][r][c4 * 4], W + (size_t)(n0 + r) * K + k0 + c4 * 4);
            }
        }
        cp_commit();

        const int buf = kt % 3;
        #pragma unroll
        for (int kk = 0; kk < 4; kk++) {
            const int kb = kk * 8;
            uint32_t a[2][4], b[8][2];
            #pragma unroll
            for (int mi = 0; mi < 2; mi++) {
                int row = wm + mi * 16;
                a[mi][0] = raw(As[buf][row + g][kb + t]);
                a[mi][1] = raw(As[buf][row + 8 + g][kb + t]);
                a[mi][2] = raw(As[buf][row + g][kb + 4 + t]);
                a[mi][3] = raw(As[buf][row + 8 + g][kb + 4 + t]);
            }
            #pragma unroll
            for (int ni = 0; ni < 8; ni++) {
                int col = wn + ni * 8;
                b[ni][0] = raw(Ws[buf][col + g][kb + t]);
                b[ni][1] = raw(Ws[buf][col + g][kb + 4 + t]);
            }
            #pragma unroll
            for (int mi = 0; mi < 2; mi++)
                #pragma unroll
                for (int ni = 0; ni < 8; ni++)
                    mma_tf32(acc[mi][ni], a[mi][0], a[mi][1], a[mi][2], a[mi][3],
                             b[ni][0], b[ni][1]);
        }
    }

    #pragma unroll
    for (int mi = 0; mi < 2; mi++) {
        #pragma unroll
        for (int ni = 0; ni < 8; ni++) {
            int m = m0 + wm + mi * 16 + g;
            int n = n0 + wn + ni * 8 + t * 2;
            float b0 = __ldg(&bias[n]), b1 = __ldg(&bias[n + 1]);
            float v0 = acc[mi][ni][0] + b0;
            float v1 = acc[mi][ni][1] + b1;
            float v2 = acc[mi][ni][2] + b0;
            float v3 = acc[mi][ni][3] + b1;
            if (mode == 0) {
                C[(size_t)m * N + n]           = v0;
                C[(size_t)m * N + n + 1]       = v1;
                C[(size_t)(m + 8) * N + n]     = v2;
                C[(size_t)(m + 8) * N + n + 1] = v3;
            } else if (mode == 2) {
                C[(size_t)m * N + n]           = rnd(v0);
                C[(size_t)m * N + n + 1]       = rnd(v1);
                C[(size_t)(m + 8) * N + n]     = rnd(v2);
                C[(size_t)(m + 8) * N + n + 1] = rnd(v3);
            } else {
                int nb = n & ~7;
                int p0 = nb + (((n & 3) << 1) | ((n >> 2) & 1));
                int p1 = p0 + 2;
                C[(size_t)m * N + p0]       = rnd(v0);
                C[(size_t)m * N + p1]       = rnd(v1);
                C[(size_t)(m + 8) * N + p0] = rnd(v2);
                C[(size_t)(m + 8) * N + p1] = rnd(v3);
            }
        }
    }
}

// Fused QKV projection: blockIdx.z selects {Wq->g_q sigma, Wk->g_k sigma,
// Wv->g_v plain}. One launch, 1152 blocks.
__global__ __launch_bounds__(256, 2)
void gemm_qkv_tc(const float* __restrict__ A,
                 const float* __restrict__ bq,
                 const float* __restrict__ bk,
                 const float* __restrict__ bv) {
    extern __shared__ __align__(16) float sm[];
    const int z = blockIdx.z;
    const float* W    = (z == 0) ? g_wq : (z == 1) ? g_wk : g_wv;
    const float* bias = (z == 0) ? bq   : (z == 1) ? bk   : bv;
    float* C          = (z == 0) ? g_q  : (z == 1) ? g_k  : g_v;
    const int mode    = (z == 2) ? 2 : 1;
    gemm_body(A, W, bias, C, MTOK, EMB, EMB,
              blockIdx.y * 128, blockIdx.x * 128, mode, sm);
}

// Output projection (plain fp32 store).
__global__ __launch_bounds__(256, 2)
void gemm_out_tc(const float* __restrict__ A,
                 const float* __restrict__ bias,
                 float* __restrict__ C) {
    extern __shared__ __align__(16) float sm[];
    gemm_body(A, g_wo, bias, C, MTOK, EMB, EMB,
              blockIdx.y * 128, blockIdx.x * 128, 0, sm);
}

// ---------------------------------------------------------------------------
// Q a-fragments (sigma-permuted g_q): LDG.64 pairs.
// ---------------------------------------------------------------------------
__device__ __forceinline__ void load_q_frags(uint32_t qa[2][8][4],
                                             int b, int h, int qbase,
                                             int g, int t) {
    #pragma unroll
    for (int mi = 0; mi < 2; mi++) {
        const float* qp = g_q + (size_t)(b * SEQ + qbase + mi * 16) * EMB + h * HDIM;
        #pragma unroll
        for (int d8 = 0; d8 < 8; d8++) {
            int c = d8 * 8 + 2 * t;
            float2 lo = *(const float2*)&qp[(size_t)g * EMB + c];
            float2 hi = *(const float2*)&qp[(size_t)(8 + g) * EMB + c];
            qa[mi][d8][0] = raw(lo.x);
            qa[mi][d8][1] = raw(hi.x);
            qa[mi][d8][2] = raw(lo.y);
            qa[mi][d8][3] = raw(hi.y);
        }
    }
}

// ---------------------------------------------------------------------------
// rowsum: g_inv = 1/rowsum(exp(QK^T*scale)). Q in regs; K smem LDS.64.
// ---------------------------------------------------------------------------
__global__ __launch_bounds__(256, 2)
void rowsum_tc() {
    extern __shared__ __align__(16) float sm[];
    float* Ks = sm;                       // [2][64][KSTR]
    __shared__ float s_red[128];

    const int bh = blockIdx.y;
    const int b  = bh / HEADS;
    const int h  = bh % HEADS;
    const int q0 = blockIdx.x * 128;
    const int tid = threadIdx.x;
    const int wid = tid >> 5;
    const int lane = tid & 31;
    const int wm = (wid >> 1) * 32;
    const int wn = (wid & 1) * 32;
    const int g = lane >> 2;
    const int t = lane & 3;

    if (tid < 128) s_red[tid] = 0.f;

    #pragma unroll
    for (int i = 0; i < 4; i++) {
        int idx = tid + i * 256, r = idx >> 4, c4 = idx & 15;
        cp16(&Ks[r * KSTR + c4 * 4],
             g_k + (size_t)(b * SEQ + r) * EMB + h * HDIM + c4 * 4);
    }
    cp_commit();

    uint32_t qa[2][8][4];
    load_q_frags(qa, b, h, q0 + wm, g, t);

    float rsum[2][2] = {};

    for (int kt = 0; kt < SEQ / 64; kt++) {
        cp_wait0();
        __syncthreads();

        if (kt + 1 < SEQ / 64) {
            float* Kn = Ks + ((kt + 1) & 1) * 64 * KSTR;
            const int r0 = (kt + 1) * 64;
            #pragma unroll
            for (int i = 0; i < 4; i++) {
                int idx = tid + i * 256, r = idx >> 4, c4 = idx & 15;
                cp16(&Kn[r * KSTR + c4 * 4],
                     g_k + (size_t)(b * SEQ + r0 + r) * EMB + h * HDIM + c4 * 4);
            }
            cp_commit();
        }

        const float* Kb = Ks + (kt & 1) * 64 * KSTR;
        float acc[2][4][4] = {};

        #pragma unroll
        for (int d8 = 0; d8 < 8; d8++) {
            const int kb = d8 * 8;
            uint32_t bb[4][2];
            #pragma unroll
            for (int ni = 0; ni < 4; ni++) {
                int col = wn + ni * 8;
                float2 kv = *(const float2*)&Kb[(col + g) * KSTR + kb + 2 * t];
                bb[ni][0] = raw(kv.x);
                bb[ni][1] = raw(kv.y);
            }
            #pragma unroll
            for (int mi = 0; mi < 2; mi++)
                #pragma unroll
                for (int ni = 0; ni < 4; ni++)
                    mma_tf32(acc[mi][ni],
                             qa[mi][d8][0], qa[mi][d8][1], qa[mi][d8][2], qa[mi][d8][3],
                             bb[ni][0], bb[ni][1]);
        }

        #pragma unroll
        for (int mi = 0; mi < 2; mi++)
            #pragma unroll
            for (int ni = 0; ni < 4; ni++) {
                rsum[mi][0] += __expf(acc[mi][ni][0] * SCALE_F)
                             + __expf(acc[mi][ni][1] * SCALE_F);
                rsum[mi][1] += __expf(acc[mi][ni][2] * SCALE_F)
                             + __expf(acc[mi][ni][3] * SCALE_F);
            }
    }

    #pragma unroll
    for (int mi = 0; mi < 2; mi++)
        #pragma unroll
        for (int j = 0; j < 2; j++) {
            rsum[mi][j] += __shfl_xor_sync(0xffffffffu, rsum[mi][j], 1);
            rsum[mi][j] += __shfl_xor_sync(0xffffffffu, rsum[mi][j], 2);
        }

    if (t == 0) {
        #pragma unroll
        for (int mi = 0; mi < 2; mi++) {
            atomicAdd(&s_red[wm + mi * 16 + g],     rsum[mi][0]);
            atomicAdd(&s_red[wm + mi * 16 + 8 + g], rsum[mi][1]);
        }
    }
    __syncthreads();
    if (tid < 128)
        g_inv[(size_t)bh * SEQ + q0 + tid] = 1.0f / s_red[tid];
}

// ---------------------------------------------------------------------------
// flash: scores (Q regs, K LDS.64), p -> gmem from c-frags + frag-major Ps;
// PV a-frags LDS.128.
// ---------------------------------------------------------------------------
__global__ __launch_bounds__(256, 2)
void flash_pv_tc(float* __restrict__ wbuf) {
    extern __shared__ __align__(16) float sm[];
    float* Ks = sm;                               // [2][64][KSTR]
    float* Vs = Ks + 2 * 64 * KSTR;               // [2][64][VSTR]
    float* Ps = Vs + 2 * 64 * VSTR;               // [32][PSBLK]

    const int bh = blockIdx.y;
    const int b  = bh / HEADS;
    const int h  = bh % HEADS;
    const int q0 = blockIdx.x * 64;
    const int tid = threadIdx.x;
    const int wid = tid >> 5;
    const int lane = tid & 31;
    const int wm = (wid >> 2) * 32;
    const int wn = (wid & 3) * 16;
    const int g = lane >> 2;
    const int t = lane & 3;

    #pragma unroll
    for (int i = 0; i < 4; i++) {
        int idx = tid + i * 256, r = idx >> 4, c4 = idx & 15;
        cp16(&Ks[r * KSTR + c4 * 4],
             g_k + (size_t)(b * SEQ + r) * EMB + h * HDIM + c4 * 4);
        cp16(&Vs[r * VSTR + c4 * 4],
             g_v + (size_t)(b * SEQ + r) * EMB + h * HDIM + c4 * 4);
    }
    cp_commit();

    uint32_t qa[2][8][4];
    load_q_frags(qa, b, h, q0 + wm, g, t);

    float iv[2][2];
    #pragma unroll
    for (int mi = 0; mi < 2; mi++) {
        iv[mi][0] = g_inv[(size_t)bh * SEQ + q0 + wm + mi * 16 + g];
        iv[mi][1] = g_inv[(size_t)bh * SEQ + q0 + wm + mi * 16 + 8 + g];
    }

    float* prow = wbuf + (size_t)bh * SEQ * SEQ;
    float acc_o[2][2][4] = {};

    const int tp0 = (2 * t) & 3;
    const int tp1 = (2 * t + 1) & 3;
    const int j0  = 2 * (t >> 1);

    for (int kt = 0; kt < SEQ / 64; kt++) {
        cp_wait0();
        __syncthreads();

        if (kt + 1 < SEQ / 64) {
            const int nb = (kt + 1) & 1;
            const int r0 = (kt + 1) * 64;
            float* Kn = Ks + nb * 64 * KSTR;
            float* Vn = Vs + nb * 64 * VSTR;
            #pragma unroll
            for (int i = 0; i < 4; i++) {
                int idx = tid + i * 256, r = idx >> 4, c4 = idx & 15;
                cp16(&Kn[r * KSTR + c4 * 4],
                     g_k + (size_t)(b * SEQ + r0 + r) * EMB + h * HDIM + c4 * 4);
                cp16(&Vn[r * VSTR + c4 * 4],
                     g_v + (size_t)(b * SEQ + r0 + r) * EMB + h * HDIM + c4 * 4);
            }
            cp_commit();
        }

        const float* Kb = Ks + (kt & 1) * 64 * KSTR;
        const float* Vb = Vs + (kt & 1) * 64 * VSTR;

        float acc_s[2][2][4] = {};
        #pragma unroll
        for (int d8 = 0; d8 < 8; d8++) {
            const int kb = d8 * 8;
            uint32_t bb[2][2];
            #pragma unroll
            for (int ni = 0; ni < 2; ni++) {
                int col = wn + ni * 8;
                float2 kv = *(const float2*)&Kb[(col + g) * KSTR + kb + 2 * t];
                bb[ni][0] = raw(kv.x);
                bb[ni][1] = raw(kv.y);
            }
            #pragma unroll
            for (int mi = 0; mi < 2; mi++)
                #pragma unroll
                for (int ni = 0; ni < 2; ni++)
                    mma_tf32(acc_s[mi][ni],
                             qa[mi][d8][0], qa[mi][d8][1], qa[mi][d8][2], qa[mi][d8][3],
                             bb[ni][0], bb[ni][1]);
        }

        #pragma unroll
        for (int mi = 0; mi < 2; mi++) {
            const int mt = (wm >> 4) + mi;
            const int r0g = q0 + wm + mi * 16 + g;
            #pragma unroll
            for (int ni = 0; ni < 2; ni++) {
                const int c0 = wn + ni * 8 + 2 * t;
                const int chunk = (wn >> 3) + ni;
                float p00 = rnd(__expf(acc_s[mi][ni][0] * SCALE_F) * iv[mi][0]);
                float p01 = rnd(__expf(acc_s[mi][ni][1] * SCALE_F) * iv[mi][0]);
                float p10 = rnd(__expf(acc_s[mi][ni][2] * SCALE_F) * iv[mi][1]);
                float p11 = rnd(__expf(acc_s[mi][ni][3] * SCALE_F) * iv[mi][1]);
                *(float2*)&prow[(size_t)r0g * SEQ + kt * 64 + c0]       = make_float2(p00, p01);
                *(float2*)&prow[(size_t)(r0g + 8) * SEQ + kt * 64 + c0] = make_float2(p10, p11);
                float* pb = &Ps[(mt * 8 + chunk) * PSBLK];
                *(float2*)&pb[(g * 4 + tp0) * 4 + j0] = make_float2(p00, p10);
                *(float2*)&pb[(g * 4 + tp1) * 4 + j0] = make_float2(p01, p11);
            }
        }
        __syncthreads();

        #pragma unroll
        for (int d8 = 0; d8 < 8; d8++) {
            const int kb = d8 * 8;
            uint32_t a[2][4];
            #pragma unroll
            for (int mi = 0; mi < 2; mi++) {
                const int mt = (wm >> 4) + mi;
                float4 av = *(const float4*)&Ps[(mt * 8 + d8) * PSBLK + lane * 4];
                a[mi][0] = raw(av.x);
                a[mi][1] = raw(av.y);
                a[mi][2] = raw(av.z);
                a[mi][3] = raw(av.w);
            }
            uint32_t bb[2][2];
            #pragma unroll
            for (int ni = 0; ni < 2; ni++) {
                int col = wn + ni * 8;
                bb[ni][0] = raw(Vb[(kb + t) * VSTR + col + g]);
                bb[ni][1] = raw(Vb[(kb + 4 + t) * VSTR + col + g]);
            }
            #pragma unroll
            for (int mi = 0; mi < 2; mi++)
                #pragma unroll
                for (int ni = 0; ni < 2; ni++)
                    mma_tf32(acc_o[mi][ni], a[mi][0], a[mi][1], a[mi][2], a[mi][3],
                             bb[ni][0], bb[ni][1]);
        }
    }

    #pragma unroll
    for (int mi = 0; mi < 2; mi++) {
        #pragma unroll
        for (int ni = 0; ni < 2; ni++) {
            int m = q0 + wm + mi * 16 + g;
            int d = wn + ni * 8 + t * 2;
            g_att[(size_t)(b * SEQ + m) * EMB + h * HDIM + d]         = rnd(acc_o[mi][ni][0]);
            g_att[(size_t)(b * SEQ + m) * EMB + h * HDIM + d + 1]     = rnd(acc_o[mi][ni][1]);
            g_att[(size_t)(b * SEQ + m + 8) * EMB + h * HDIM + d]     = rnd(acc_o[mi][ni][2]);
            g_att[(size_t)(b * SEQ + m + 8) * EMB + h * HDIM + d + 1] = rnd(acc_o[mi][ni][3]);
        }
    }
}

// ---------------------------------------------------------------------------
// launch
// ---------------------------------------------------------------------------
extern "C" void kernel_launch(void* const* d_in, const int* in_sizes, int n_in,
                              void* d_out, int out_size) {
    (void)in_sizes; (void)n_in; (void)out_size;

    const float* hs = (const float*)d_in[0];
    const float* Wq = (const float*)d_in[1];
    const float* bq = (const float*)d_in[2];
    const float* Wk = (const float*)d_in[3];
    const float* bk = (const float*)d_in[4];
    const float* Wv = (const float*)d_in[5];
    const float* bv = (const float*)d_in[6];
    const float* Wo = (const float*)d_in[7];
    const float* bo = (const float*)d_in[8];

    float* out      = (float*)d_out;
    float* attn_out = out;
    float* wbuf     = out + (size_t)MTOK * EMB;

    float* datt, * dhsr, * dwq, * dwk, * dwv, * dwo;
    cudaGetSymbolAddress((void**)&datt, g_att);
    cudaGetSymbolAddress((void**)&dhsr, g_hsr);
    cudaGetSymbolAddress((void**)&dwq,  g_wq);
    cudaGetSymbolAddress((void**)&dwk,  g_wk);
    cudaGetSymbolAddress((void**)&dwv,  g_wv);
    cudaGetSymbolAddress((void**)&dwo,  g_wo);

    const int smem_gemm  = (3 * 128 * PAD + 3 * 128 * PAD) * 4;                 // 110592
    const int smem_rsum  = (2 * 64 * KSTR) * 4;                                 // 36864
    const int smem_flash = (2 * 64 * KSTR + 2 * 64 * VSTR + 32 * PSBLK) * 4;    // 90624

    cudaFuncSetAttribute(gemm_qkv_tc, cudaFuncAttributeMaxDynamicSharedMemorySize, smem_gemm);
    cudaFuncSetAttribute(gemm_out_tc, cudaFuncAttributeMaxDynamicSharedMemorySize, smem_gemm);
    cudaFuncSetAttribute(rowsum_tc,   cudaFuncAttributeMaxDynamicSharedMemorySize, smem_rsum);
    cudaFuncSetAttribute(flash_pv_tc, cudaFuncAttributeMaxDynamicSharedMemorySize, smem_flash);

    // fused pre-round (hs + 4 weights), one launch
    const int n4_hs = MTOK * EMB / 4;
    const int n4_w  = EMB * EMB / 4;
    const int n4_total = n4_hs + 4 * n4_w;
    round_all_kernel<<<(n4_total + 255) / 256, 256>>>(
        (const float4*)hs, (const float4*)Wq, (const float4*)Wk,
        (const float4*)Wv, (const float4*)Wo,
        (float4*)dhsr, (float4*)dwq, (float4*)dwk, (float4*)dwv, (float4*)dwo,
        n4_hs, n4_w);

    // fused QKV projections: one launch, grid.z = 3
    gemm_qkv_tc<<<dim3(EMB / 128, MTOK / 128, 3), 256, smem_gemm>>>(dhsr, bq, bk, bv);

    rowsum_tc<<<dim3(SEQ / 128, BH), 256, smem_rsum>>>();

    flash_pv_tc<<<dim3(SEQ / 64, BH), 256, smem_flash>>>(wbuf);

    gemm_out_tc<<<dim3(EMB / 128, MTOK / 128), 256, smem_gemm>>>(datt, bo, attn_out);
}